// round 1
// baseline (speedup 1.0000x reference)
#include <cuda_runtime.h>

// Problem constants
#define CB 4
#define CT 2048
#define CD 2048
#define CH 16
#define CHD 128
#define QKVD (3 * CD)   // 6144

// Scratch (allocation-free rule: __device__ globals)
__device__ float g_qkv[(size_t)CB * CT * QKVD];   // [b, t, 6144]  (q | k | v)
__device__ float g_y[(size_t)CB * CT * CD];       // [b, t, h*128+hd]

// ---------------------------------------------------------------------------
// Generic NT SGEMM: C[M,N] = A[M,K] @ B[N,K]^T  (both operands K-contiguous)
// 128x128 tile, BK=8, 256 threads, 8x8 per-thread microtile.
// M, N divisible by 128; K divisible by 8 (true for all uses here).
// ---------------------------------------------------------------------------
__global__ __launch_bounds__(256) void sgemm_nt(
    const float* __restrict__ A, const float* __restrict__ Bm,
    float* __restrict__ C, int M, int N, int K)
{
    __shared__ float As[8][128];
    __shared__ float Bs[8][128];

    const int tid = threadIdx.x;
    const int tx = tid & 15;        // 0..15 -> N direction
    const int ty = tid >> 4;        // 0..15 -> M direction
    const int rowBase = blockIdx.y * 128;
    const int colBase = blockIdx.x * 128;

    const int lr = tid >> 1;              // 0..127: tile row loaded
    const int lk = (tid & 1) << 2;        // 0 or 4: k offset (float4)
    const float* Ap = A + (size_t)(rowBase + lr) * K + lk;
    const float* Bp = Bm + (size_t)(colBase + lr) * K + lk;

    float acc[8][8];
#pragma unroll
    for (int i = 0; i < 8; i++)
#pragma unroll
        for (int j = 0; j < 8; j++) acc[i][j] = 0.0f;

    for (int kt = 0; kt < K; kt += 8) {
        float4 av = *(const float4*)(Ap + kt);
        float4 bv = *(const float4*)(Bp + kt);
        As[lk + 0][lr] = av.x; As[lk + 1][lr] = av.y;
        As[lk + 2][lr] = av.z; As[lk + 3][lr] = av.w;
        Bs[lk + 0][lr] = bv.x; Bs[lk + 1][lr] = bv.y;
        Bs[lk + 2][lr] = bv.z; Bs[lk + 3][lr] = bv.w;
        __syncthreads();

#pragma unroll
        for (int k = 0; k < 8; k++) {
            float a[8], b[8];
            *(float4*)(a)     = *(const float4*)&As[k][ty * 8];
            *(float4*)(a + 4) = *(const float4*)&As[k][ty * 8 + 4];
            *(float4*)(b)     = *(const float4*)&Bs[k][tx * 8];
            *(float4*)(b + 4) = *(const float4*)&Bs[k][tx * 8 + 4];
#pragma unroll
            for (int i = 0; i < 8; i++)
#pragma unroll
                for (int j = 0; j < 8; j++)
                    acc[i][j] = fmaf(a[i], b[j], acc[i][j]);
        }
        __syncthreads();
    }

#pragma unroll
    for (int i = 0; i < 8; i++) {
        float* Cp = C + (size_t)(rowBase + ty * 8 + i) * N + colBase + tx * 8;
        *(float4*)(Cp)     = make_float4(acc[i][0], acc[i][1], acc[i][2], acc[i][3]);
        *(float4*)(Cp + 4) = make_float4(acc[i][4], acc[i][5], acc[i][6], acc[i][7]);
    }
}

// ---------------------------------------------------------------------------
// Fused flash attention (fp32, online softmax).
// Block: 256 threads handles one (b,h) x 64-query tile; loops 64-key tiles.
// Thread (tx,ty): 4 query rows (ty*4+i), d-columns {tx*4..tx*4+3, 64+tx*4..+3},
// and 4 key columns (tx*4+j) during the S phase.
// ---------------------------------------------------------------------------
#define QS_STRIDE 132
#define PS_STRIDE 65
#define FLASH_SMEM_FLOATS (3 * 64 * QS_STRIDE + 64 * PS_STRIDE)
#define FLASH_SMEM_BYTES (FLASH_SMEM_FLOATS * 4)

__global__ __launch_bounds__(256) void flash_attn(
    const float* __restrict__ qkv, const int* __restrict__ mask,
    float* __restrict__ y)
{
    extern __shared__ float sm[];
    float* Qs = sm;                       // 64 x 132
    float* Ks = Qs + 64 * QS_STRIDE;      // 64 x 132
    float* Vs = Ks + 64 * QS_STRIDE;      // 64 x 132
    float* Ps = Vs + 64 * QS_STRIDE;      // 64 x 65

    const int qt = blockIdx.x;            // 0..31 (query tile)
    const int bh = blockIdx.y;            // 0..63
    const int b = bh / CH;
    const int h = bh % CH;

    const int tid = threadIdx.x;
    const int tx = tid & 15;
    const int ty = tid >> 4;

    const size_t baseQ = (size_t)b * CT * QKVD + (size_t)h * CHD;
    const size_t baseK = baseQ + CD;
    const size_t baseV = baseQ + 2 * CD;
    const int q0 = qt * 64;

    // Load Q tile: 64 rows x 128 floats = 2048 float4 / 256 threads = 8 each
    for (int i = tid; i < 64 * 32; i += 256) {
        int r = i >> 5;
        int c = (i & 31) * 4;
        float4 v = *(const float4*)(qkv + baseQ + (size_t)(q0 + r) * QKVD + c);
        *(float4*)&Qs[r * QS_STRIDE + c] = v;
    }

    float acc[4][8];
    float mrow[4], lrow[4];
#pragma unroll
    for (int i = 0; i < 4; i++) {
        mrow[i] = -1e30f;
        lrow[i] = 0.0f;
#pragma unroll
        for (int d = 0; d < 8; d++) acc[i][d] = 0.0f;
    }
    const float scale = 0.08838834764831845f;   // 1/sqrt(128)

    for (int kt0 = 0; kt0 < CT; kt0 += 64) {
        __syncthreads();   // protect Q (first iter) / prev-iter K,V,P consumers

        // Load K and V tiles
        for (int i = tid; i < 64 * 32; i += 256) {
            int r = i >> 5;
            int c = (i & 31) * 4;
            *(float4*)&Ks[r * QS_STRIDE + c] =
                *(const float4*)(qkv + baseK + (size_t)(kt0 + r) * QKVD + c);
            *(float4*)&Vs[r * QS_STRIDE + c] =
                *(const float4*)(qkv + baseV + (size_t)(kt0 + r) * QKVD + c);
        }
        __syncthreads();

        // S = Q @ K^T for this tile
        float s[4][4];
#pragma unroll
        for (int i = 0; i < 4; i++)
#pragma unroll
            for (int j = 0; j < 4; j++) s[i][j] = 0.0f;

#pragma unroll 4
        for (int kk = 0; kk < CHD; kk += 4) {
            float4 qv[4], kv[4];
#pragma unroll
            for (int i = 0; i < 4; i++)
                qv[i] = *(const float4*)&Qs[(ty * 4 + i) * QS_STRIDE + kk];
#pragma unroll
            for (int j = 0; j < 4; j++)
                kv[j] = *(const float4*)&Ks[(tx * 4 + j) * QS_STRIDE + kk];
#pragma unroll
            for (int i = 0; i < 4; i++)
#pragma unroll
                for (int j = 0; j < 4; j++) {
                    s[i][j] = fmaf(qv[i].x, kv[j].x, s[i][j]);
                    s[i][j] = fmaf(qv[i].y, kv[j].y, s[i][j]);
                    s[i][j] = fmaf(qv[i].z, kv[j].z, s[i][j]);
                    s[i][j] = fmaf(qv[i].w, kv[j].w, s[i][j]);
                }
        }

        // mask + scale
        int mk[4];
#pragma unroll
        for (int j = 0; j < 4; j++)
            mk[j] = mask[b * CT + kt0 + tx * 4 + j];
#pragma unroll
        for (int i = 0; i < 4; i++)
#pragma unroll
            for (int j = 0; j < 4; j++)
                s[i][j] = mk[j] ? s[i][j] * scale : -1e30f;

        // Online softmax per query row; reductions across the 16-lane tx group
#pragma unroll
        for (int i = 0; i < 4; i++) {
            float tm = fmaxf(fmaxf(s[i][0], s[i][1]), fmaxf(s[i][2], s[i][3]));
#pragma unroll
            for (int m = 8; m >= 1; m >>= 1)
                tm = fmaxf(tm, __shfl_xor_sync(0xffffffffu, tm, m));
            float mnew = fmaxf(mrow[i], tm);
            float corr = __expf(mrow[i] - mnew);
            float psum = 0.0f;
#pragma unroll
            for (int j = 0; j < 4; j++) {
                float p = __expf(s[i][j] - mnew);
                s[i][j] = p;
                psum += p;
            }
#pragma unroll
            for (int m = 8; m >= 1; m >>= 1)
                psum += __shfl_xor_sync(0xffffffffu, psum, m);
            lrow[i] = lrow[i] * corr + psum;
            mrow[i] = mnew;
#pragma unroll
            for (int d = 0; d < 8; d++) acc[i][d] *= corr;
#pragma unroll
            for (int j = 0; j < 4; j++)
                Ps[(ty * 4 + i) * PS_STRIDE + tx * 4 + j] = s[i][j];
        }
        __syncthreads();

        // acc += P @ V  (thread d-columns: tx*4..+3 and 64+tx*4..+3)
#pragma unroll 2
        for (int k = 0; k < 64; k++) {
            float4 v0 = *(const float4*)&Vs[k * QS_STRIDE + tx * 4];
            float4 v1 = *(const float4*)&Vs[k * QS_STRIDE + 64 + tx * 4];
#pragma unroll
            for (int i = 0; i < 4; i++) {
                float p = Ps[(ty * 4 + i) * PS_STRIDE + k];
                acc[i][0] = fmaf(p, v0.x, acc[i][0]);
                acc[i][1] = fmaf(p, v0.y, acc[i][1]);
                acc[i][2] = fmaf(p, v0.z, acc[i][2]);
                acc[i][3] = fmaf(p, v0.w, acc[i][3]);
                acc[i][4] = fmaf(p, v1.x, acc[i][4]);
                acc[i][5] = fmaf(p, v1.y, acc[i][5]);
                acc[i][6] = fmaf(p, v1.z, acc[i][6]);
                acc[i][7] = fmaf(p, v1.w, acc[i][7]);
            }
        }
    }

    // Normalize and store y[b, q, h*128 + d]
#pragma unroll
    for (int i = 0; i < 4; i++) {
        int q = q0 + ty * 4 + i;
        float inv = 1.0f / lrow[i];
        float* yp = y + (size_t)(b * CT + q) * CD + h * CHD;
        *(float4*)(yp + tx * 4) =
            make_float4(acc[i][0] * inv, acc[i][1] * inv, acc[i][2] * inv, acc[i][3] * inv);
        *(float4*)(yp + 64 + tx * 4) =
            make_float4(acc[i][4] * inv, acc[i][5] * inv, acc[i][6] * inv, acc[i][7] * inv);
    }
}

// ---------------------------------------------------------------------------
extern "C" void kernel_launch(void* const* d_in, const int* in_sizes, int n_in,
                              void* d_out, int out_size)
{
    const float* x      = (const float*)d_in[0];
    const int*   mask   = (const int*)d_in[1];
    const float* w_qkv  = (const float*)d_in[2];
    const float* w_o    = (const float*)d_in[3];
    float*       out    = (float*)d_out;

    float* qkv = nullptr;
    float* y   = nullptr;
    cudaGetSymbolAddress((void**)&qkv, g_qkv);
    cudaGetSymbolAddress((void**)&y, g_y);

    // 1) qkv = x @ w_qkv^T : M=8192, N=6144, K=2048
    {
        dim3 grid(QKVD / 128, (CB * CT) / 128);
        sgemm_nt<<<grid, 256>>>(x, w_qkv, qkv, CB * CT, QKVD, CD);
    }

    // 2) fused attention -> y
    {
        cudaFuncSetAttribute(flash_attn,
                             cudaFuncAttributeMaxDynamicSharedMemorySize,
                             FLASH_SMEM_BYTES);
        dim3 grid(CT / 64, CB * CH);
        flash_attn<<<grid, 256, FLASH_SMEM_BYTES>>>(qkv, mask, y);
    }

    // 3) out = y @ w_o^T : M=8192, N=2048, K=2048
    {
        dim3 grid(CD / 128, (CB * CT) / 128);
        sgemm_nt<<<grid, 256>>>(y, w_o, out, CB * CT, CD, CD);
    }
}

// round 3
// speedup vs baseline: 1.4152x; 1.4152x over previous
#include <cuda_runtime.h>
#include <cstdint>

// Problem constants
#define CB 4
#define CT 2048
#define CD 2048
#define CH 16
#define CHD 128
#define QKVD (3 * CD)   // 6144

// Scratch (allocation-free rule: __device__ globals)
__device__ float g_qkv[(size_t)CB * CT * QKVD];   // [b, t, 6144]  (q | k | v)
__device__ float g_y[(size_t)CB * CT * CD];       // [b, t, h*128+hd]

__device__ __forceinline__ uint32_t f2tf32(float f) {
    uint32_t r;
    asm("cvt.rna.tf32.f32 %0, %1;" : "=r"(r) : "f"(f));
    return r;
}

__device__ __forceinline__ void mma_tf32(
    float& c0, float& c1, float& c2, float& c3,
    uint32_t a0, uint32_t a1, uint32_t a2, uint32_t a3,
    uint32_t b0, uint32_t b1)
{
    asm volatile(
        "mma.sync.aligned.m16n8k8.row.col.f32.tf32.tf32.f32 "
        "{%0,%1,%2,%3}, {%4,%5,%6,%7}, {%8,%9}, {%0,%1,%2,%3};"
        : "+f"(c0), "+f"(c1), "+f"(c2), "+f"(c3)
        : "r"(a0), "r"(a1), "r"(a2), "r"(a3), "r"(b0), "r"(b1));
}

// ===========================================================================
// Tensor-core (mma.sync tf32) NT GEMM: C[M,N] = A[M,K] @ B[N,K]^T
// CTA tile 128x128, BK=16, 256 threads = 8 warps (4 m x 2 n).
// Warp tile 32(m) x 64(n): 2 m16 tiles x 8 n8 tiles.
// Stride-20 smem layout -> all fragment LDS conflict-free.
// ===========================================================================
#define SA_STRIDE 20

__global__ __launch_bounds__(256, 1) void sgemm_tc(
    const float* __restrict__ A, const float* __restrict__ Bm,
    float* __restrict__ C, int M, int N, int K)
{
    __shared__ uint32_t As[128 * SA_STRIDE];
    __shared__ uint32_t Bs[128 * SA_STRIDE];

    const int tid = threadIdx.x;
    const int wid = tid >> 5;
    const int lane = tid & 31;
    const int g = lane >> 2;      // 0..7
    const int q = lane & 3;       // 0..3

    const int warp_m = wid & 3;           // 0..3 -> m offset *32
    const int warp_n = wid >> 2;          // 0..1 -> n offset *64

    const int rowBase = blockIdx.y * 128;
    const int colBase = blockIdx.x * 128;

    // Global load mapping: each thread 2 float4 per operand
    const int lrow = tid >> 2;            // 0..63
    const int lcol = (tid & 3) * 4;       // 0,4,8,12
    const float* Ap0 = A + (size_t)(rowBase + lrow) * K + lcol;
    const float* Ap1 = A + (size_t)(rowBase + lrow + 64) * K + lcol;
    const float* Bp0 = Bm + (size_t)(colBase + lrow) * K + lcol;
    const float* Bp1 = Bm + (size_t)(colBase + lrow + 64) * K + lcol;

    float acc[2][8][4];
#pragma unroll
    for (int mt = 0; mt < 2; mt++)
#pragma unroll
        for (int nt = 0; nt < 8; nt++)
#pragma unroll
            for (int c = 0; c < 4; c++) acc[mt][nt][c] = 0.0f;

    const int nstages = K >> 4;   // K/16

    // Prefetch stage 0
    float4 ra0 = *(const float4*)(Ap0);
    float4 ra1 = *(const float4*)(Ap1);
    float4 rb0 = *(const float4*)(Bp0);
    float4 rb1 = *(const float4*)(Bp1);

    for (int s = 0; s < nstages; s++) {
        __syncthreads();   // previous iteration's compute done

        // Store (converted to tf32) into smem
        *(uint4*)&As[lrow * SA_STRIDE + lcol] =
            make_uint4(f2tf32(ra0.x), f2tf32(ra0.y), f2tf32(ra0.z), f2tf32(ra0.w));
        *(uint4*)&As[(lrow + 64) * SA_STRIDE + lcol] =
            make_uint4(f2tf32(ra1.x), f2tf32(ra1.y), f2tf32(ra1.z), f2tf32(ra1.w));
        *(uint4*)&Bs[lrow * SA_STRIDE + lcol] =
            make_uint4(f2tf32(rb0.x), f2tf32(rb0.y), f2tf32(rb0.z), f2tf32(rb0.w));
        *(uint4*)&Bs[(lrow + 64) * SA_STRIDE + lcol] =
            make_uint4(f2tf32(rb1.x), f2tf32(rb1.y), f2tf32(rb1.z), f2tf32(rb1.w));
        __syncthreads();

        // Prefetch next stage
        if (s + 1 < nstages) {
            const int koff = (s + 1) << 4;
            ra0 = *(const float4*)(Ap0 + koff);
            ra1 = *(const float4*)(Ap1 + koff);
            rb0 = *(const float4*)(Bp0 + koff);
            rb1 = *(const float4*)(Bp1 + koff);
        }

        // Compute: 2 k8 sub-steps
#pragma unroll
        for (int kk = 0; kk < 16; kk += 8) {
            uint32_t afr[2][4];
#pragma unroll
            for (int mt = 0; mt < 2; mt++) {
                const int m0 = warp_m * 32 + mt * 16;
                afr[mt][0] = As[(m0 + g) * SA_STRIDE + kk + q];
                afr[mt][1] = As[(m0 + g + 8) * SA_STRIDE + kk + q];
                afr[mt][2] = As[(m0 + g) * SA_STRIDE + kk + q + 4];
                afr[mt][3] = As[(m0 + g + 8) * SA_STRIDE + kk + q + 4];
            }
#pragma unroll
            for (int nt = 0; nt < 8; nt++) {
                const int n0 = warp_n * 64 + nt * 8;
                uint32_t b0 = Bs[(n0 + g) * SA_STRIDE + kk + q];
                uint32_t b1 = Bs[(n0 + g) * SA_STRIDE + kk + q + 4];
#pragma unroll
                for (int mt = 0; mt < 2; mt++)
                    mma_tf32(acc[mt][nt][0], acc[mt][nt][1],
                             acc[mt][nt][2], acc[mt][nt][3],
                             afr[mt][0], afr[mt][1], afr[mt][2], afr[mt][3],
                             b0, b1);
            }
        }
    }

    // Epilogue: c0:(g,2q) c1:(g,2q+1) c2:(g+8,2q) c3:(g+8,2q+1)
#pragma unroll
    for (int mt = 0; mt < 2; mt++) {
        const int m0 = rowBase + warp_m * 32 + mt * 16;
#pragma unroll
        for (int nt = 0; nt < 8; nt++) {
            const int n0 = colBase + warp_n * 64 + nt * 8;
            *(float2*)(C + (size_t)(m0 + g) * N + n0 + 2 * q) =
                make_float2(acc[mt][nt][0], acc[mt][nt][1]);
            *(float2*)(C + (size_t)(m0 + g + 8) * N + n0 + 2 * q) =
                make_float2(acc[mt][nt][2], acc[mt][nt][3]);
        }
    }
}

// ---------------------------------------------------------------------------
// Fused flash attention (fp32, online softmax). Unchanged from R1.
// ---------------------------------------------------------------------------
#define QS_STRIDE 132
#define PS_STRIDE 65
#define FLASH_SMEM_FLOATS (3 * 64 * QS_STRIDE + 64 * PS_STRIDE)
#define FLASH_SMEM_BYTES (FLASH_SMEM_FLOATS * 4)

__global__ __launch_bounds__(256) void flash_attn(
    const float* __restrict__ qkv, const int* __restrict__ mask,
    float* __restrict__ y)
{
    extern __shared__ float sm[];
    float* Qs = sm;                       // 64 x 132
    float* Ks = Qs + 64 * QS_STRIDE;      // 64 x 132
    float* Vs = Ks + 64 * QS_STRIDE;      // 64 x 132
    float* Ps = Vs + 64 * QS_STRIDE;      // 64 x 65

    const int qt = blockIdx.x;
    const int bh = blockIdx.y;
    const int b = bh / CH;
    const int h = bh % CH;

    const int tid = threadIdx.x;
    const int tx = tid & 15;
    const int ty = tid >> 4;

    const size_t baseQ = (size_t)b * CT * QKVD + (size_t)h * CHD;
    const size_t baseK = baseQ + CD;
    const size_t baseV = baseQ + 2 * CD;
    const int q0 = qt * 64;

    for (int i = tid; i < 64 * 32; i += 256) {
        int r = i >> 5;
        int c = (i & 31) * 4;
        float4 v = *(const float4*)(qkv + baseQ + (size_t)(q0 + r) * QKVD + c);
        *(float4*)&Qs[r * QS_STRIDE + c] = v;
    }

    float acc[4][8];
    float mrow[4], lrow[4];
#pragma unroll
    for (int i = 0; i < 4; i++) {
        mrow[i] = -1e30f;
        lrow[i] = 0.0f;
#pragma unroll
        for (int d = 0; d < 8; d++) acc[i][d] = 0.0f;
    }
    const float scale = 0.08838834764831845f;   // 1/sqrt(128)

    for (int kt0 = 0; kt0 < CT; kt0 += 64) {
        __syncthreads();

        for (int i = tid; i < 64 * 32; i += 256) {
            int r = i >> 5;
            int c = (i & 31) * 4;
            *(float4*)&Ks[r * QS_STRIDE + c] =
                *(const float4*)(qkv + baseK + (size_t)(kt0 + r) * QKVD + c);
            *(float4*)&Vs[r * QS_STRIDE + c] =
                *(const float4*)(qkv + baseV + (size_t)(kt0 + r) * QKVD + c);
        }
        __syncthreads();

        float s[4][4];
#pragma unroll
        for (int i = 0; i < 4; i++)
#pragma unroll
            for (int j = 0; j < 4; j++) s[i][j] = 0.0f;

#pragma unroll 4
        for (int kk = 0; kk < CHD; kk += 4) {
            float4 qv[4], kv[4];
#pragma unroll
            for (int i = 0; i < 4; i++)
                qv[i] = *(const float4*)&Qs[(ty * 4 + i) * QS_STRIDE + kk];
#pragma unroll
            for (int j = 0; j < 4; j++)
                kv[j] = *(const float4*)&Ks[(tx * 4 + j) * QS_STRIDE + kk];
#pragma unroll
            for (int i = 0; i < 4; i++)
#pragma unroll
                for (int j = 0; j < 4; j++) {
                    s[i][j] = fmaf(qv[i].x, kv[j].x, s[i][j]);
                    s[i][j] = fmaf(qv[i].y, kv[j].y, s[i][j]);
                    s[i][j] = fmaf(qv[i].z, kv[j].z, s[i][j]);
                    s[i][j] = fmaf(qv[i].w, kv[j].w, s[i][j]);
                }
        }

        int mk[4];
#pragma unroll
        for (int j = 0; j < 4; j++)
            mk[j] = mask[b * CT + kt0 + tx * 4 + j];
#pragma unroll
        for (int i = 0; i < 4; i++)
#pragma unroll
            for (int j = 0; j < 4; j++)
                s[i][j] = mk[j] ? s[i][j] * scale : -1e30f;

#pragma unroll
        for (int i = 0; i < 4; i++) {
            float tm = fmaxf(fmaxf(s[i][0], s[i][1]), fmaxf(s[i][2], s[i][3]));
#pragma unroll
            for (int m = 8; m >= 1; m >>= 1)
                tm = fmaxf(tm, __shfl_xor_sync(0xffffffffu, tm, m));
            float mnew = fmaxf(mrow[i], tm);
            float corr = __expf(mrow[i] - mnew);
            float psum = 0.0f;
#pragma unroll
            for (int j = 0; j < 4; j++) {
                float p = __expf(s[i][j] - mnew);
                s[i][j] = p;
                psum += p;
            }
#pragma unroll
            for (int m = 8; m >= 1; m >>= 1)
                psum += __shfl_xor_sync(0xffffffffu, psum, m);
            lrow[i] = lrow[i] * corr + psum;
            mrow[i] = mnew;
#pragma unroll
            for (int d = 0; d < 8; d++) acc[i][d] *= corr;
#pragma unroll
            for (int j = 0; j < 4; j++)
                Ps[(ty * 4 + i) * PS_STRIDE + tx * 4 + j] = s[i][j];
        }
        __syncthreads();

#pragma unroll 2
        for (int k = 0; k < 64; k++) {
            float4 v0 = *(const float4*)&Vs[k * QS_STRIDE + tx * 4];
            float4 v1 = *(const float4*)&Vs[k * QS_STRIDE + 64 + tx * 4];
#pragma unroll
            for (int i = 0; i < 4; i++) {
                float p = Ps[(ty * 4 + i) * PS_STRIDE + k];
                acc[i][0] = fmaf(p, v0.x, acc[i][0]);
                acc[i][1] = fmaf(p, v0.y, acc[i][1]);
                acc[i][2] = fmaf(p, v0.z, acc[i][2]);
                acc[i][3] = fmaf(p, v0.w, acc[i][3]);
                acc[i][4] = fmaf(p, v1.x, acc[i][4]);
                acc[i][5] = fmaf(p, v1.y, acc[i][5]);
                acc[i][6] = fmaf(p, v1.z, acc[i][6]);
                acc[i][7] = fmaf(p, v1.w, acc[i][7]);
            }
        }
    }

#pragma unroll
    for (int i = 0; i < 4; i++) {
        int q = q0 + ty * 4 + i;
        float inv = 1.0f / lrow[i];
        float* yp = y + (size_t)(b * CT + q) * CD + h * CHD;
        *(float4*)(yp + tx * 4) =
            make_float4(acc[i][0] * inv, acc[i][1] * inv, acc[i][2] * inv, acc[i][3] * inv);
        *(float4*)(yp + 64 + tx * 4) =
            make_float4(acc[i][4] * inv, acc[i][5] * inv, acc[i][6] * inv, acc[i][7] * inv);
    }
}

// ---------------------------------------------------------------------------
extern "C" void kernel_launch(void* const* d_in, const int* in_sizes, int n_in,
                              void* d_out, int out_size)
{
    const float* x      = (const float*)d_in[0];
    const int*   mask   = (const int*)d_in[1];
    const float* w_qkv  = (const float*)d_in[2];
    const float* w_o    = (const float*)d_in[3];
    float*       out    = (float*)d_out;

    float* qkv = nullptr;
    float* y   = nullptr;
    cudaGetSymbolAddress((void**)&qkv, g_qkv);
    cudaGetSymbolAddress((void**)&y, g_y);

    cudaFuncSetAttribute(flash_attn,
                         cudaFuncAttributeMaxDynamicSharedMemorySize,
                         FLASH_SMEM_BYTES);

    // 1) qkv = x @ w_qkv^T : M=8192, N=6144, K=2048  (mma.sync tf32)
    {
        dim3 grid(QKVD / 128, (CB * CT) / 128);
        sgemm_tc<<<grid, 256>>>(x, w_qkv, qkv, CB * CT, QKVD, CD);
    }

    // 2) fused attention -> y (fp32)
    {
        dim3 grid(CT / 64, CB * CH);
        flash_attn<<<grid, 256, FLASH_SMEM_BYTES>>>(qkv, mask, y);
    }

    // 3) out = y @ w_o^T : M=8192, N=2048, K=2048  (mma.sync tf32)
    {
        dim3 grid(CD / 128, (CB * CT) / 128);
        sgemm_tc<<<grid, 256>>>(y, w_o, out, CB * CT, CD, CD);
    }
}

// round 6
// speedup vs baseline: 4.2183x; 2.9807x over previous
#include <cuda_runtime.h>
#include <cstdint>

// Problem constants
#define CB 4
#define CT 2048
#define CD 2048
#define CH 16
#define CHD 128
#define QKVD (3 * CD)   // 6144

// Scratch (allocation-free rule: __device__ globals)
__device__ float g_qkv[(size_t)CB * CT * QKVD];   // [b, t, 6144]  (q | k | v)
__device__ float g_y[(size_t)CB * CT * CD];       // [b, t, h*128+hd]

__device__ __forceinline__ uint32_t f2tf32(float f) {
    uint32_t r;
    asm("cvt.rna.tf32.f32 %0, %1;" : "=r"(r) : "f"(f));
    return r;
}

__device__ __forceinline__ float ex2(float x) {
    float r;
    asm("ex2.approx.f32 %0, %1;" : "=f"(r) : "f"(x));
    return r;
}

__device__ __forceinline__ void mma_tf32(
    float& c0, float& c1, float& c2, float& c3,
    uint32_t a0, uint32_t a1, uint32_t a2, uint32_t a3,
    uint32_t b0, uint32_t b1)
{
    asm volatile(
        "mma.sync.aligned.m16n8k8.row.col.f32.tf32.tf32.f32 "
        "{%0,%1,%2,%3}, {%4,%5,%6,%7}, {%8,%9}, {%0,%1,%2,%3};"
        : "+f"(c0), "+f"(c1), "+f"(c2), "+f"(c3)
        : "r"(a0), "r"(a1), "r"(a2), "r"(a3), "r"(b0), "r"(b1));
}

// ===========================================================================
// Tensor-core (mma.sync tf32) NT GEMM: C[M,N] = A[M,K] @ B[N,K]^T
// CTA tile 128x128, BK=16, 256 threads = 8 warps (4 m x 2 n).
// Double-buffered smem, single __syncthreads per stage, LDG overlapped.
// ===========================================================================
#define SA_STRIDE 20

__global__ __launch_bounds__(256, 2) void sgemm_tc(
    const float* __restrict__ A, const float* __restrict__ Bm,
    float* __restrict__ C, int M, int N, int K)
{
    __shared__ uint32_t As[2][128 * SA_STRIDE];
    __shared__ uint32_t Bs[2][128 * SA_STRIDE];

    const int tid = threadIdx.x;
    const int wid = tid >> 5;
    const int lane = tid & 31;
    const int g = lane >> 2;      // 0..7
    const int q = lane & 3;       // 0..3

    const int warp_m = wid & 3;           // 0..3 -> m offset *32
    const int warp_n = wid >> 2;          // 0..1 -> n offset *64

    const int rowBase = blockIdx.y * 128;
    const int colBase = blockIdx.x * 128;

    const int lrow = tid >> 2;            // 0..63
    const int lcol = (tid & 3) * 4;       // 0,4,8,12
    const float* Ap0 = A + (size_t)(rowBase + lrow) * K + lcol;
    const float* Ap1 = A + (size_t)(rowBase + lrow + 64) * K + lcol;
    const float* Bp0 = Bm + (size_t)(colBase + lrow) * K + lcol;
    const float* Bp1 = Bm + (size_t)(colBase + lrow + 64) * K + lcol;

    float acc[2][8][4];
#pragma unroll
    for (int mt = 0; mt < 2; mt++)
#pragma unroll
        for (int nt = 0; nt < 8; nt++)
#pragma unroll
            for (int c = 0; c < 4; c++) acc[mt][nt][c] = 0.0f;

    const int nstages = K >> 4;   // K/16

    // Prologue: stage 0 into buffer 0
    float4 ra0 = *(const float4*)(Ap0);
    float4 ra1 = *(const float4*)(Ap1);
    float4 rb0 = *(const float4*)(Bp0);
    float4 rb1 = *(const float4*)(Bp1);
    *(uint4*)&As[0][lrow * SA_STRIDE + lcol] =
        make_uint4(f2tf32(ra0.x), f2tf32(ra0.y), f2tf32(ra0.z), f2tf32(ra0.w));
    *(uint4*)&As[0][(lrow + 64) * SA_STRIDE + lcol] =
        make_uint4(f2tf32(ra1.x), f2tf32(ra1.y), f2tf32(ra1.z), f2tf32(ra1.w));
    *(uint4*)&Bs[0][lrow * SA_STRIDE + lcol] =
        make_uint4(f2tf32(rb0.x), f2tf32(rb0.y), f2tf32(rb0.z), f2tf32(rb0.w));
    *(uint4*)&Bs[0][(lrow + 64) * SA_STRIDE + lcol] =
        make_uint4(f2tf32(rb1.x), f2tf32(rb1.y), f2tf32(rb1.z), f2tf32(rb1.w));
    __syncthreads();

    for (int s = 0; s < nstages; s++) {
        const int buf = s & 1;

        // Issue next-stage global loads early (latency hidden by compute)
        if (s + 1 < nstages) {
            const int koff = (s + 1) << 4;
            ra0 = *(const float4*)(Ap0 + koff);
            ra1 = *(const float4*)(Ap1 + koff);
            rb0 = *(const float4*)(Bp0 + koff);
            rb1 = *(const float4*)(Bp1 + koff);
        }

        // Compute on current buffer
#pragma unroll
        for (int kk = 0; kk < 16; kk += 8) {
            uint32_t afr[2][4];
#pragma unroll
            for (int mt = 0; mt < 2; mt++) {
                const int m0 = warp_m * 32 + mt * 16;
                afr[mt][0] = As[buf][(m0 + g) * SA_STRIDE + kk + q];
                afr[mt][1] = As[buf][(m0 + g + 8) * SA_STRIDE + kk + q];
                afr[mt][2] = As[buf][(m0 + g) * SA_STRIDE + kk + q + 4];
                afr[mt][3] = As[buf][(m0 + g + 8) * SA_STRIDE + kk + q + 4];
            }
#pragma unroll
            for (int nt = 0; nt < 8; nt++) {
                const int n0 = warp_n * 64 + nt * 8;
                uint32_t b0 = Bs[buf][(n0 + g) * SA_STRIDE + kk + q];
                uint32_t b1 = Bs[buf][(n0 + g) * SA_STRIDE + kk + q + 4];
#pragma unroll
                for (int mt = 0; mt < 2; mt++)
                    mma_tf32(acc[mt][nt][0], acc[mt][nt][1],
                             acc[mt][nt][2], acc[mt][nt][3],
                             afr[mt][0], afr[mt][1], afr[mt][2], afr[mt][3],
                             b0, b1);
            }
        }

        // Stage s+1 into the other buffer (safe: buf^1 was fully consumed
        // before the sync that ended iteration s-1)
        if (s + 1 < nstages) {
            const int nb = buf ^ 1;
            *(uint4*)&As[nb][lrow * SA_STRIDE + lcol] =
                make_uint4(f2tf32(ra0.x), f2tf32(ra0.y), f2tf32(ra0.z), f2tf32(ra0.w));
            *(uint4*)&As[nb][(lrow + 64) * SA_STRIDE + lcol] =
                make_uint4(f2tf32(ra1.x), f2tf32(ra1.y), f2tf32(ra1.z), f2tf32(ra1.w));
            *(uint4*)&Bs[nb][lrow * SA_STRIDE + lcol] =
                make_uint4(f2tf32(rb0.x), f2tf32(rb0.y), f2tf32(rb0.z), f2tf32(rb0.w));
            *(uint4*)&Bs[nb][(lrow + 64) * SA_STRIDE + lcol] =
                make_uint4(f2tf32(rb1.x), f2tf32(rb1.y), f2tf32(rb1.z), f2tf32(rb1.w));
            __syncthreads();
        }
    }

    // Epilogue: c0:(g,2q) c1:(g,2q+1) c2:(g+8,2q) c3:(g+8,2q+1)
#pragma unroll
    for (int mt = 0; mt < 2; mt++) {
        const int m0 = rowBase + warp_m * 32 + mt * 16;
#pragma unroll
        for (int nt = 0; nt < 8; nt++) {
            const int n0 = colBase + warp_n * 64 + nt * 8;
            *(float2*)(C + (size_t)(m0 + g) * N + n0 + 2 * q) =
                make_float2(acc[mt][nt][0], acc[mt][nt][1]);
            *(float2*)(C + (size_t)(m0 + g + 8) * N + n0 + 2 * q) =
                make_float2(acc[mt][nt][2], acc[mt][nt][3]);
        }
    }
}

// ===========================================================================
// Tensor-core flash attention (tf32 mma, online softmax, exp2 domain).
// Block: 256 threads = 8 warps. Q-tile 128, K-tile 64.
// Warp w owns query rows [w*16, w*16+16).
//   S phase: warp computes S(16 x 64) = Q(16x128) @ K^T   (8 n8-tiles)
//   PV phase: warp computes O(16 x 128) += P(16x64) @ V   (16 n8-tiles)
// P round-trips through warp-private smem slice (no block sync needed).
// scale * log2(e) folded into Q at load; softmax uses ex2.
// ===========================================================================
#define FQ 128
#define FKT 64
#define QST 132   // Q/K smem stride (conflict-free frag LDS: 132%32 == 4)
#define VST 136   // V smem stride   (conflict-free b-frag LDS: 136%32 == 8)
#define PST 68    // P smem stride

#define FLASH_SMEM_FLOATS (FQ * QST + FKT * QST + FKT * VST + FQ * PST + FKT)
#define FLASH_SMEM_BYTES (FLASH_SMEM_FLOATS * 4)

__global__ __launch_bounds__(256, 1) void flash_attn_tc(
    const float* __restrict__ qkv, const int* __restrict__ mask,
    float* __restrict__ y)
{
    extern __shared__ uint32_t smu[];
    uint32_t* Qs = smu;                       // FQ x QST (tf32 bits)
    uint32_t* Ks = Qs + FQ * QST;             // FKT x QST
    uint32_t* Vs = Ks + FKT * QST;            // FKT x VST
    uint32_t* Ps = Vs + FKT * VST;            // FQ x PST
    float* bias = (float*)(Ps + FQ * PST);    // FKT

    const int qt = blockIdx.x;                // 0..15
    const int bh = blockIdx.y;                // 0..63
    const int b = bh / CH;
    const int h = bh % CH;

    const int tid = threadIdx.x;
    const int wid = tid >> 5;                 // 0..7
    const int lane = tid & 31;
    const int g = lane >> 2;                  // 0..7
    const int q = lane & 3;                   // 0..3
    const int m0 = wid * 16;                  // warp's query-row base

    const size_t baseQ = (size_t)b * CT * QKVD + (size_t)h * CHD;
    const size_t baseK = baseQ + CD;
    const size_t baseV = baseQ + 2 * CD;
    const int q0 = qt * FQ;

    // Load Q tile (scaled by 1/sqrt(HD) * log2(e), tf32)
    const float qscale = 0.08838834764831845f * 1.4426950408889634f;
#pragma unroll
    for (int i = 0; i < 16; i++) {
        int idx = i * 256 + tid;
        int r = idx >> 5;
        int c = (idx & 31) * 4;
        float4 v = *(const float4*)(qkv + baseQ + (size_t)(q0 + r) * QKVD + c);
        *(uint4*)&Qs[r * QST + c] = make_uint4(
            f2tf32(v.x * qscale), f2tf32(v.y * qscale),
            f2tf32(v.z * qscale), f2tf32(v.w * qscale));
    }

    float acc[16][4];
#pragma unroll
    for (int nt = 0; nt < 16; nt++)
#pragma unroll
        for (int c = 0; c < 4; c++) acc[nt][c] = 0.0f;
    float m_r0 = -1e30f, m_r1 = -1e30f;
    float l_r0 = 0.0f, l_r1 = 0.0f;

    for (int kt0 = 0; kt0 < CT; kt0 += FKT) {
        __syncthreads();   // prev iter's PV done reading V/P; Q ready (first)

        // Load K and V tiles (tf32)
#pragma unroll
        for (int i = 0; i < 8; i++) {
            int idx = i * 256 + tid;
            int r = idx >> 5;
            int c = (idx & 31) * 4;
            float4 kv = *(const float4*)(qkv + baseK + (size_t)(kt0 + r) * QKVD + c);
            float4 vv = *(const float4*)(qkv + baseV + (size_t)(kt0 + r) * QKVD + c);
            *(uint4*)&Ks[r * QST + c] = make_uint4(
                f2tf32(kv.x), f2tf32(kv.y), f2tf32(kv.z), f2tf32(kv.w));
            *(uint4*)&Vs[r * VST + c] = make_uint4(
                f2tf32(vv.x), f2tf32(vv.y), f2tf32(vv.z), f2tf32(vv.w));
        }
        if (tid < FKT)
            bias[tid] = mask[b * CT + kt0 + tid] ? 0.0f : -1e30f;
        __syncthreads();

        // ---- S = Q @ K^T (16 x 64 per warp) ----
        float s[8][4];
#pragma unroll
        for (int nt = 0; nt < 8; nt++)
#pragma unroll
            for (int c = 0; c < 4; c++) s[nt][c] = 0.0f;

#pragma unroll
        for (int ks = 0; ks < 16; ks++) {
            const int kk = ks * 8;
            uint32_t a0 = Qs[(m0 + g) * QST + kk + q];
            uint32_t a1 = Qs[(m0 + g + 8) * QST + kk + q];
            uint32_t a2 = Qs[(m0 + g) * QST + kk + q + 4];
            uint32_t a3 = Qs[(m0 + g + 8) * QST + kk + q + 4];
#pragma unroll
            for (int nt = 0; nt < 8; nt++) {
                uint32_t b0 = Ks[(nt * 8 + g) * QST + kk + q];
                uint32_t b1 = Ks[(nt * 8 + g) * QST + kk + q + 4];
                mma_tf32(s[nt][0], s[nt][1], s[nt][2], s[nt][3],
                         a0, a1, a2, a3, b0, b1);
            }
        }

        // mask bias (cols 2q, 2q+1 of each n8 tile)
#pragma unroll
        for (int nt = 0; nt < 8; nt++) {
            float2 bb = *(const float2*)&bias[nt * 8 + 2 * q];
            s[nt][0] += bb.x; s[nt][1] += bb.y;
            s[nt][2] += bb.x; s[nt][3] += bb.y;
        }

        // row maxes (rows g and g+8), reduce over q lanes
        float tm0 = -1e30f, tm1 = -1e30f;
#pragma unroll
        for (int nt = 0; nt < 8; nt++) {
            tm0 = fmaxf(tm0, fmaxf(s[nt][0], s[nt][1]));
            tm1 = fmaxf(tm1, fmaxf(s[nt][2], s[nt][3]));
        }
        tm0 = fmaxf(tm0, __shfl_xor_sync(0xffffffffu, tm0, 1));
        tm0 = fmaxf(tm0, __shfl_xor_sync(0xffffffffu, tm0, 2));
        tm1 = fmaxf(tm1, __shfl_xor_sync(0xffffffffu, tm1, 1));
        tm1 = fmaxf(tm1, __shfl_xor_sync(0xffffffffu, tm1, 2));

        const float mn0 = fmaxf(m_r0, tm0);
        const float mn1 = fmaxf(m_r1, tm1);
        const float corr0 = ex2(m_r0 - mn0);
        const float corr1 = ex2(m_r1 - mn1);
        m_r0 = mn0; m_r1 = mn1;

        // exp, partial sums, store P (tf32) to warp-private smem slice
        float ps0 = 0.0f, ps1 = 0.0f;
#pragma unroll
        for (int nt = 0; nt < 8; nt++) {
            float p0 = ex2(s[nt][0] - mn0);
            float p1 = ex2(s[nt][1] - mn0);
            float p2 = ex2(s[nt][2] - mn1);
            float p3 = ex2(s[nt][3] - mn1);
            ps0 += p0 + p1;
            ps1 += p2 + p3;
            *(uint2*)&Ps[(m0 + g) * PST + nt * 8 + 2 * q] =
                make_uint2(f2tf32(p0), f2tf32(p1));
            *(uint2*)&Ps[(m0 + g + 8) * PST + nt * 8 + 2 * q] =
                make_uint2(f2tf32(p2), f2tf32(p3));
        }
        ps0 += __shfl_xor_sync(0xffffffffu, ps0, 1);
        ps0 += __shfl_xor_sync(0xffffffffu, ps0, 2);
        ps1 += __shfl_xor_sync(0xffffffffu, ps1, 1);
        ps1 += __shfl_xor_sync(0xffffffffu, ps1, 2);
        l_r0 = l_r0 * corr0 + ps0;
        l_r1 = l_r1 * corr1 + ps1;

        // rescale accumulators
#pragma unroll
        for (int nt = 0; nt < 16; nt++) {
            acc[nt][0] *= corr0; acc[nt][1] *= corr0;
            acc[nt][2] *= corr1; acc[nt][3] *= corr1;
        }
        __syncwarp();   // P store -> P load (warp-local)

        // ---- O += P @ V (16 x 128 per warp) ----
#pragma unroll
        for (int ks = 0; ks < 8; ks++) {
            const int kk = ks * 8;
            uint32_t a0 = Ps[(m0 + g) * PST + kk + q];
            uint32_t a1 = Ps[(m0 + g + 8) * PST + kk + q];
            uint32_t a2 = Ps[(m0 + g) * PST + kk + q + 4];
            uint32_t a3 = Ps[(m0 + g + 8) * PST + kk + q + 4];
#pragma unroll
            for (int nt = 0; nt < 16; nt++) {
                uint32_t b0 = Vs[(kk + q) * VST + nt * 8 + g];
                uint32_t b1 = Vs[(kk + q + 4) * VST + nt * 8 + g];
                mma_tf32(acc[nt][0], acc[nt][1], acc[nt][2], acc[nt][3],
                         a0, a1, a2, a3, b0, b1);
            }
        }
    }

    // Normalize and write y[b, q0+row, h*128 + col]
    const float inv0 = 1.0f / l_r0;
    const float inv1 = 1.0f / l_r1;
    const int row0 = q0 + m0 + g;
    const int row1 = row0 + 8;
    float* y0 = y + (size_t)(b * CT + row0) * CD + h * CHD;
    float* y1 = y + (size_t)(b * CT + row1) * CD + h * CHD;
#pragma unroll
    for (int nt = 0; nt < 16; nt++) {
        const int col = nt * 8 + 2 * q;
        *(float2*)(y0 + col) = make_float2(acc[nt][0] * inv0, acc[nt][1] * inv0);
        *(float2*)(y1 + col) = make_float2(acc[nt][2] * inv1, acc[nt][3] * inv1);
    }
}

// ---------------------------------------------------------------------------
extern "C" void kernel_launch(void* const* d_in, const int* in_sizes, int n_in,
                              void* d_out, int out_size)
{
    const float* x      = (const float*)d_in[0];
    const int*   mask   = (const int*)d_in[1];
    const float* w_qkv  = (const float*)d_in[2];
    const float* w_o    = (const float*)d_in[3];
    float*       out    = (float*)d_out;

    float* qkv = nullptr;
    float* y   = nullptr;
    cudaGetSymbolAddress((void**)&qkv, g_qkv);
    cudaGetSymbolAddress((void**)&y, g_y);

    cudaFuncSetAttribute(flash_attn_tc,
                         cudaFuncAttributeMaxDynamicSharedMemorySize,
                         FLASH_SMEM_BYTES);

    // 1) qkv = x @ w_qkv^T : M=8192, N=6144, K=2048  (mma.sync tf32)
    {
        dim3 grid(QKVD / 128, (CB * CT) / 128);
        sgemm_tc<<<grid, 256>>>(x, w_qkv, qkv, CB * CT, QKVD, CD);
    }

    // 2) fused attention -> y (mma.sync tf32)
    {
        dim3 grid(CT / FQ, CB * CH);
        flash_attn_tc<<<grid, 256, FLASH_SMEM_BYTES>>>(qkv, mask, y);
    }

    // 3) out = y @ w_o^T : M=8192, N=2048, K=2048  (mma.sync tf32)
    {
        dim3 grid(CD / 128, (CB * CT) / 128);
        sgemm_tc<<<grid, 256>>>(y, w_o, out, CB * CT, CD, CD);
    }
}

// round 10
// speedup vs baseline: 4.3454x; 1.0301x over previous
#include <cuda_runtime.h>
#include <cstdint>

// Problem constants
#define CB 4
#define CT 2048
#define CD 2048
#define CH 16
#define CHD 128
#define QKVD (3 * CD)   // 6144

// Scratch (allocation-free rule: __device__ globals)
__device__ float g_qkv[(size_t)CB * CT * QKVD];   // [b, t, 6144]  (q | k | v)
__device__ float g_y[(size_t)CB * CT * CD];       // [b, t, h*128+hd]

__device__ __forceinline__ uint32_t f2tf32(float f) {
    uint32_t r;
    asm("cvt.rna.tf32.f32 %0, %1;" : "=r"(r) : "f"(f));
    return r;
}

__device__ __forceinline__ float ex2(float x) {
    float r;
    asm("ex2.approx.f32 %0, %1;" : "=f"(r) : "f"(x));
    return r;
}

__device__ __forceinline__ void mma_tf32(
    float& c0, float& c1, float& c2, float& c3,
    uint32_t a0, uint32_t a1, uint32_t a2, uint32_t a3,
    uint32_t b0, uint32_t b1)
{
    asm volatile(
        "mma.sync.aligned.m16n8k8.row.col.f32.tf32.tf32.f32 "
        "{%0,%1,%2,%3}, {%4,%5,%6,%7}, {%8,%9}, {%0,%1,%2,%3};"
        : "+f"(c0), "+f"(c1), "+f"(c2), "+f"(c3)
        : "r"(a0), "r"(a1), "r"(a2), "r"(a3), "r"(b0), "r"(b1));
}

// ldmatrix x4: four 8x8-b16 (= 8x4-b32) tiles; lane L<8 supplies row addrs of
// tile0, 8..15 tile1, 16..23 tile2, 24..31 tile3.
__device__ __forceinline__ void ldsm_x4(
    uint32_t& r0, uint32_t& r1, uint32_t& r2, uint32_t& r3, uint32_t addr)
{
    asm volatile(
        "ldmatrix.sync.aligned.m8n8.x4.shared.b16 {%0,%1,%2,%3}, [%4];"
        : "=r"(r0), "=r"(r1), "=r"(r2), "=r"(r3) : "r"(addr));
}

// Per-lane byte offset for an A-fragment ldmatrix (m16 x k8 tile):
// tile0: rows m..m+7 col kk | tile1: rows m+8.. col kk | tile2/3: col kk+4
__device__ __forceinline__ uint32_t a_lane_off(int lane, int strideW) {
    return (uint32_t)((((lane & 7) + ((lane >> 3) & 1) * 8) * strideW
                       + (lane >> 4) * 4) * 4);
}
// Per-lane byte offset for a B-fragment ldmatrix covering 2 n8 tiles:
// tile0: rows n..n+7 col kk (b0) | tile1: same rows col kk+4 (b1)
// tile2: rows n+8..n+15 col kk  | tile3: col kk+4
__device__ __forceinline__ uint32_t b_lane_off(int lane, int strideW) {
    return (uint32_t)(((((lane >> 4) & 1) * 8 + (lane & 7)) * strideW
                       + ((lane >> 3) & 1) * 4) * 4);
}

// ===========================================================================
// Tensor-core (mma.sync tf32) NT GEMM: C[M,N] = A[M,K] @ B[N,K]^T
// CTA tile 128x128, BK=16, 256 threads = 8 warps (4 m x 2 n).
// Double-buffered smem, single __syncthreads per stage, LDG overlapped,
// ldmatrix fragment loads.
// ===========================================================================
#define SA_STRIDE 20
#define SGEMM_BUF_BYTES (128 * SA_STRIDE * 4)

__global__ __launch_bounds__(256, 2) void sgemm_tc(
    const float* __restrict__ A, const float* __restrict__ Bm,
    float* __restrict__ C, int M, int N, int K)
{
    __shared__ uint32_t As[2][128 * SA_STRIDE];
    __shared__ uint32_t Bs[2][128 * SA_STRIDE];

    const int tid = threadIdx.x;
    const int wid = tid >> 5;
    const int lane = tid & 31;
    const int g = lane >> 2;      // 0..7
    const int q = lane & 3;       // 0..3

    const int warp_m = wid & 3;           // 0..3 -> m offset *32
    const int warp_n = wid >> 2;          // 0..1 -> n offset *64

    const int rowBase = blockIdx.y * 128;
    const int colBase = blockIdx.x * 128;

    const int lrow = tid >> 2;            // 0..63
    const int lcol = (tid & 3) * 4;       // 0,4,8,12
    const float* Ap0 = A + (size_t)(rowBase + lrow) * K + lcol;
    const float* Ap1 = A + (size_t)(rowBase + lrow + 64) * K + lcol;
    const float* Bp0 = Bm + (size_t)(colBase + lrow) * K + lcol;
    const float* Bp1 = Bm + (size_t)(colBase + lrow + 64) * K + lcol;

    const uint32_t aSm = (uint32_t)__cvta_generic_to_shared(&As[0][0]);
    const uint32_t bSm = (uint32_t)__cvta_generic_to_shared(&Bs[0][0]);
    // ldmatrix base addresses (buffer 0) for this lane
    const uint32_t aFrag0 = aSm + a_lane_off(lane, SA_STRIDE)
                          + (uint32_t)(warp_m * 32 * SA_STRIDE * 4);
    const uint32_t bFrag0 = bSm + b_lane_off(lane, SA_STRIDE)
                          + (uint32_t)(warp_n * 64 * SA_STRIDE * 4);

    float acc[2][8][4];
#pragma unroll
    for (int mt = 0; mt < 2; mt++)
#pragma unroll
        for (int nt = 0; nt < 8; nt++)
#pragma unroll
            for (int c = 0; c < 4; c++) acc[mt][nt][c] = 0.0f;

    const int nstages = K >> 4;   // K/16

    // Prologue: stage 0 into buffer 0
    float4 ra0 = *(const float4*)(Ap0);
    float4 ra1 = *(const float4*)(Ap1);
    float4 rb0 = *(const float4*)(Bp0);
    float4 rb1 = *(const float4*)(Bp1);
    *(uint4*)&As[0][lrow * SA_STRIDE + lcol] =
        make_uint4(f2tf32(ra0.x), f2tf32(ra0.y), f2tf32(ra0.z), f2tf32(ra0.w));
    *(uint4*)&As[0][(lrow + 64) * SA_STRIDE + lcol] =
        make_uint4(f2tf32(ra1.x), f2tf32(ra1.y), f2tf32(ra1.z), f2tf32(ra1.w));
    *(uint4*)&Bs[0][lrow * SA_STRIDE + lcol] =
        make_uint4(f2tf32(rb0.x), f2tf32(rb0.y), f2tf32(rb0.z), f2tf32(rb0.w));
    *(uint4*)&Bs[0][(lrow + 64) * SA_STRIDE + lcol] =
        make_uint4(f2tf32(rb1.x), f2tf32(rb1.y), f2tf32(rb1.z), f2tf32(rb1.w));
    __syncthreads();

    for (int s = 0; s < nstages; s++) {
        const int buf = s & 1;
        const uint32_t bufOff = (uint32_t)(buf * SGEMM_BUF_BYTES);

        // Issue next-stage global loads early (latency hidden by compute)
        if (s + 1 < nstages) {
            const int koff = (s + 1) << 4;
            ra0 = *(const float4*)(Ap0 + koff);
            ra1 = *(const float4*)(Ap1 + koff);
            rb0 = *(const float4*)(Bp0 + koff);
            rb1 = *(const float4*)(Bp1 + koff);
        }

        // Compute on current buffer (ldmatrix fragments)
#pragma unroll
        for (int kk = 0; kk < 16; kk += 8) {
            uint32_t afr[2][4];
#pragma unroll
            for (int mt = 0; mt < 2; mt++)
                ldsm_x4(afr[mt][0], afr[mt][1], afr[mt][2], afr[mt][3],
                        aFrag0 + bufOff
                        + (uint32_t)((mt * 16 * SA_STRIDE + kk) * 4));
#pragma unroll
            for (int ntp = 0; ntp < 4; ntp++) {
                uint32_t b0, b1, b2, b3;
                ldsm_x4(b0, b1, b2, b3,
                        bFrag0 + bufOff
                        + (uint32_t)((ntp * 16 * SA_STRIDE + kk) * 4));
#pragma unroll
                for (int mt = 0; mt < 2; mt++) {
                    mma_tf32(acc[mt][2 * ntp][0], acc[mt][2 * ntp][1],
                             acc[mt][2 * ntp][2], acc[mt][2 * ntp][3],
                             afr[mt][0], afr[mt][1], afr[mt][2], afr[mt][3],
                             b0, b1);
                    mma_tf32(acc[mt][2 * ntp + 1][0], acc[mt][2 * ntp + 1][1],
                             acc[mt][2 * ntp + 1][2], acc[mt][2 * ntp + 1][3],
                             afr[mt][0], afr[mt][1], afr[mt][2], afr[mt][3],
                             b2, b3);
                }
            }
        }

        // Stage s+1 into the other buffer
        if (s + 1 < nstages) {
            const int nb = buf ^ 1;
            *(uint4*)&As[nb][lrow * SA_STRIDE + lcol] =
                make_uint4(f2tf32(ra0.x), f2tf32(ra0.y), f2tf32(ra0.z), f2tf32(ra0.w));
            *(uint4*)&As[nb][(lrow + 64) * SA_STRIDE + lcol] =
                make_uint4(f2tf32(ra1.x), f2tf32(ra1.y), f2tf32(ra1.z), f2tf32(ra1.w));
            *(uint4*)&Bs[nb][lrow * SA_STRIDE + lcol] =
                make_uint4(f2tf32(rb0.x), f2tf32(rb0.y), f2tf32(rb0.z), f2tf32(rb0.w));
            *(uint4*)&Bs[nb][(lrow + 64) * SA_STRIDE + lcol] =
                make_uint4(f2tf32(rb1.x), f2tf32(rb1.y), f2tf32(rb1.z), f2tf32(rb1.w));
            __syncthreads();
        }
    }

    // Epilogue: c0:(g,2q) c1:(g,2q+1) c2:(g+8,2q) c3:(g+8,2q+1)
#pragma unroll
    for (int mt = 0; mt < 2; mt++) {
        const int m0 = rowBase + warp_m * 32 + mt * 16;
#pragma unroll
        for (int nt = 0; nt < 8; nt++) {
            const int n0 = colBase + warp_n * 64 + nt * 8;
            *(float2*)(C + (size_t)(m0 + g) * N + n0 + 2 * q) =
                make_float2(acc[mt][nt][0], acc[mt][nt][1]);
            *(float2*)(C + (size_t)(m0 + g + 8) * N + n0 + 2 * q) =
                make_float2(acc[mt][nt][2], acc[mt][nt][3]);
        }
    }
}

// ===========================================================================
// Tensor-core flash attention (tf32 mma, online softmax, exp2 domain).
// Block: 256 threads = 8 warps. Q-tile 128, K-tile 64. ldmatrix fragments.
// V stored TRANSPOSED in smem (Vt[d][k]) so PV B-fragments are ldmatrix-able.
// ===========================================================================
#define FQ 128
#define FKT 64
#define QST 132   // Q/K smem stride (ldmatrix rows: 132r%32=4r -> conflict-free)
#define PST 68    // P smem stride   (68r%32=4r -> conflict-free)
#define VTST 68   // Vt smem stride

#define FLASH_SMEM_FLOATS (FQ * QST + FKT * QST + CHD * VTST + FQ * PST + FKT)
#define FLASH_SMEM_BYTES (FLASH_SMEM_FLOATS * 4)

__global__ __launch_bounds__(256, 1) void flash_attn_tc(
    const float* __restrict__ qkv, const int* __restrict__ mask,
    float* __restrict__ y)
{
    extern __shared__ uint32_t smu[];
    uint32_t* Qs = smu;                       // FQ x QST (tf32 bits)
    uint32_t* Ks = Qs + FQ * QST;             // FKT x QST
    uint32_t* Vt = Ks + FKT * QST;            // CHD x VTST (transposed V)
    uint32_t* Ps = Vt + CHD * VTST;           // FQ x PST
    float* bias = (float*)(Ps + FQ * PST);    // FKT

    const int qt = blockIdx.x;                // 0..15
    const int bh = blockIdx.y;                // 0..63
    const int b = bh / CH;
    const int h = bh % CH;

    const int tid = threadIdx.x;
    const int wid = tid >> 5;                 // 0..7
    const int lane = tid & 31;
    const int g = lane >> 2;                  // 0..7
    const int q = lane & 3;                   // 0..3
    const int m0 = wid * 16;                  // warp's query-row base

    const size_t baseQ = (size_t)b * CT * QKVD + (size_t)h * CHD;
    const size_t baseK = baseQ + CD;
    const size_t baseV = baseQ + 2 * CD;
    const int q0 = qt * FQ;

    const uint32_t qSm = (uint32_t)__cvta_generic_to_shared(Qs);
    const uint32_t kSm = (uint32_t)__cvta_generic_to_shared(Ks);
    const uint32_t vSm = (uint32_t)__cvta_generic_to_shared(Vt);
    const uint32_t pSm = (uint32_t)__cvta_generic_to_shared(Ps);

    const uint32_t aQ = qSm + a_lane_off(lane, QST) + (uint32_t)(m0 * QST * 4);
    const uint32_t bK = kSm + b_lane_off(lane, QST);
    const uint32_t aP = pSm + a_lane_off(lane, PST) + (uint32_t)(m0 * PST * 4);
    const uint32_t bV = vSm + b_lane_off(lane, VTST);

    // Load Q tile (scaled by 1/sqrt(HD) * log2(e), tf32)
    const float qscale = 0.08838834764831845f * 1.4426950408889634f;
#pragma unroll
    for (int i = 0; i < 16; i++) {
        int idx = i * 256 + tid;
        int r = idx >> 5;
        int c = (idx & 31) * 4;
        float4 v = *(const float4*)(qkv + baseQ + (size_t)(q0 + r) * QKVD + c);
        *(uint4*)&Qs[r * QST + c] = make_uint4(
            f2tf32(v.x * qscale), f2tf32(v.y * qscale),
            f2tf32(v.z * qscale), f2tf32(v.w * qscale));
    }

    float acc[16][4];
#pragma unroll
    for (int nt = 0; nt < 16; nt++)
#pragma unroll
        for (int c = 0; c < 4; c++) acc[nt][c] = 0.0f;
    float m_r0 = -1e30f, m_r1 = -1e30f;
    float l_r0 = 0.0f, l_r1 = 0.0f;

    // V-load mapping: k = lane-consecutive, d-group fixed per warp
    const int vk = tid & 63;          // token within k-tile
    const int vcg_base = tid >> 6;    // 0..3

    for (int kt0 = 0; kt0 < CT; kt0 += FKT) {
        __syncthreads();   // prev iter's PV done reading Vt/Ps; Q ready (first)

        // Load K tile (row-major, tf32)
#pragma unroll
        for (int i = 0; i < 8; i++) {
            int idx = i * 256 + tid;
            int r = idx >> 5;
            int c = (idx & 31) * 4;
            float4 kv = *(const float4*)(qkv + baseK + (size_t)(kt0 + r) * QKVD + c);
            *(uint4*)&Ks[r * QST + c] = make_uint4(
                f2tf32(kv.x), f2tf32(kv.y), f2tf32(kv.z), f2tf32(kv.w));
        }
        // Load V tile TRANSPOSED: Vt[d][k]. Warp: fixed d-group, k = lane.
#pragma unroll
        for (int i = 0; i < 8; i++) {
            int cg = vcg_base + i * 4;    // 0..31
            float4 vv = *(const float4*)(qkv + baseV
                                         + (size_t)(kt0 + vk) * QKVD + cg * 4);
            Vt[(cg * 4 + 0) * VTST + vk] = f2tf32(vv.x);
            Vt[(cg * 4 + 1) * VTST + vk] = f2tf32(vv.y);
            Vt[(cg * 4 + 2) * VTST + vk] = f2tf32(vv.z);
            Vt[(cg * 4 + 3) * VTST + vk] = f2tf32(vv.w);
        }
        if (tid < FKT)
            bias[tid] = mask[b * CT + kt0 + tid] ? 0.0f : -1e30f;
        __syncthreads();

        // ---- S = Q @ K^T (16 x 64 per warp) ----
        float s[8][4];
#pragma unroll
        for (int nt = 0; nt < 8; nt++)
#pragma unroll
            for (int c = 0; c < 4; c++) s[nt][c] = 0.0f;

#pragma unroll
        for (int ks = 0; ks < 16; ks++) {
            const uint32_t kkB = (uint32_t)(ks * 8 * 4);
            uint32_t a0, a1, a2, a3;
            ldsm_x4(a0, a1, a2, a3, aQ + kkB);
#pragma unroll
            for (int ntp = 0; ntp < 4; ntp++) {
                uint32_t b0, b1, b2, b3;
                ldsm_x4(b0, b1, b2, b3,
                        bK + (uint32_t)(ntp * 16 * QST * 4) + kkB);
                mma_tf32(s[2 * ntp][0], s[2 * ntp][1],
                         s[2 * ntp][2], s[2 * ntp][3],
                         a0, a1, a2, a3, b0, b1);
                mma_tf32(s[2 * ntp + 1][0], s[2 * ntp + 1][1],
                         s[2 * ntp + 1][2], s[2 * ntp + 1][3],
                         a0, a1, a2, a3, b2, b3);
            }
        }

        // mask bias (cols 2q, 2q+1 of each n8 tile)
#pragma unroll
        for (int nt = 0; nt < 8; nt++) {
            float2 bb = *(const float2*)&bias[nt * 8 + 2 * q];
            s[nt][0] += bb.x; s[nt][1] += bb.y;
            s[nt][2] += bb.x; s[nt][3] += bb.y;
        }

        // row maxes (rows g and g+8), reduce over q lanes
        float tm0 = -1e30f, tm1 = -1e30f;
#pragma unroll
        for (int nt = 0; nt < 8; nt++) {
            tm0 = fmaxf(tm0, fmaxf(s[nt][0], s[nt][1]));
            tm1 = fmaxf(tm1, fmaxf(s[nt][2], s[nt][3]));
        }
        tm0 = fmaxf(tm0, __shfl_xor_sync(0xffffffffu, tm0, 1));
        tm0 = fmaxf(tm0, __shfl_xor_sync(0xffffffffu, tm0, 2));
        tm1 = fmaxf(tm1, __shfl_xor_sync(0xffffffffu, tm1, 1));
        tm1 = fmaxf(tm1, __shfl_xor_sync(0xffffffffu, tm1, 2));

        const float mn0 = fmaxf(m_r0, tm0);
        const float mn1 = fmaxf(m_r1, tm1);
        const float corr0 = ex2(m_r0 - mn0);
        const float corr1 = ex2(m_r1 - mn1);
        m_r0 = mn0; m_r1 = mn1;

        // exp, partial sums, store P (tf32) to warp-private smem slice
        float ps0 = 0.0f, ps1 = 0.0f;
#pragma unroll
        for (int nt = 0; nt < 8; nt++) {
            float p0 = ex2(s[nt][0] - mn0);
            float p1 = ex2(s[nt][1] - mn0);
            float p2 = ex2(s[nt][2] - mn1);
            float p3 = ex2(s[nt][3] - mn1);
            ps0 += p0 + p1;
            ps1 += p2 + p3;
            *(uint2*)&Ps[(m0 + g) * PST + nt * 8 + 2 * q] =
                make_uint2(f2tf32(p0), f2tf32(p1));
            *(uint2*)&Ps[(m0 + g + 8) * PST + nt * 8 + 2 * q] =
                make_uint2(f2tf32(p2), f2tf32(p3));
        }
        ps0 += __shfl_xor_sync(0xffffffffu, ps0, 1);
        ps0 += __shfl_xor_sync(0xffffffffu, ps0, 2);
        ps1 += __shfl_xor_sync(0xffffffffu, ps1, 1);
        ps1 += __shfl_xor_sync(0xffffffffu, ps1, 2);
        l_r0 = l_r0 * corr0 + ps0;
        l_r1 = l_r1 * corr1 + ps1;

        // rescale accumulators
#pragma unroll
        for (int nt = 0; nt < 16; nt++) {
            acc[nt][0] *= corr0; acc[nt][1] *= corr0;
            acc[nt][2] *= corr1; acc[nt][3] *= corr1;
        }
        __syncwarp();   // P store -> P ldmatrix (warp-local)

        // ---- O += P @ V (16 x 128 per warp) ----
#pragma unroll
        for (int ks = 0; ks < 8; ks++) {
            const uint32_t kkB = (uint32_t)(ks * 8 * 4);
            uint32_t a0, a1, a2, a3;
            ldsm_x4(a0, a1, a2, a3, aP + kkB);
#pragma unroll
            for (int ntp = 0; ntp < 8; ntp++) {
                uint32_t b0, b1, b2, b3;
                ldsm_x4(b0, b1, b2, b3,
                        bV + (uint32_t)(ntp * 16 * VTST * 4) + kkB);
                mma_tf32(acc[2 * ntp][0], acc[2 * ntp][1],
                         acc[2 * ntp][2], acc[2 * ntp][3],
                         a0, a1, a2, a3, b0, b1);
                mma_tf32(acc[2 * ntp + 1][0], acc[2 * ntp + 1][1],
                         acc[2 * ntp + 1][2], acc[2 * ntp + 1][3],
                         a0, a1, a2, a3, b2, b3);
            }
        }
    }

    // Normalize and write y[b, q0+row, h*128 + col]
    const float inv0 = 1.0f / l_r0;
    const float inv1 = 1.0f / l_r1;
    const int row0 = q0 + m0 + g;
    const int row1 = row0 + 8;
    float* y0 = y + (size_t)(b * CT + row0) * CD + h * CHD;
    float* y1 = y + (size_t)(b * CT + row1) * CD + h * CHD;
#pragma unroll
    for (int nt = 0; nt < 16; nt++) {
        const int col = nt * 8 + 2 * q;
        *(float2*)(y0 + col) = make_float2(acc[nt][0] * inv0, acc[nt][1] * inv0);
        *(float2*)(y1 + col) = make_float2(acc[nt][2] * inv1, acc[nt][3] * inv1);
    }
}

// ---------------------------------------------------------------------------
extern "C" void kernel_launch(void* const* d_in, const int* in_sizes, int n_in,
                              void* d_out, int out_size)
{
    const float* x      = (const float*)d_in[0];
    const int*   mask   = (const int*)d_in[1];
    const float* w_qkv  = (const float*)d_in[2];
    const float* w_o    = (const float*)d_in[3];
    float*       out    = (float*)d_out;

    float* qkv = nullptr;
    float* y   = nullptr;
    cudaGetSymbolAddress((void**)&qkv, g_qkv);
    cudaGetSymbolAddress((void**)&y, g_y);

    cudaFuncSetAttribute(flash_attn_tc,
                         cudaFuncAttributeMaxDynamicSharedMemorySize,
                         FLASH_SMEM_BYTES);

    // 1) qkv = x @ w_qkv^T : M=8192, N=6144, K=2048  (mma.sync tf32)
    {
        dim3 grid(QKVD / 128, (CB * CT) / 128);
        sgemm_tc<<<grid, 256>>>(x, w_qkv, qkv, CB * CT, QKVD, CD);
    }

    // 2) fused attention -> y (mma.sync tf32 + ldmatrix)
    {
        dim3 grid(CT / FQ, CB * CH);
        flash_attn_tc<<<grid, 256, FLASH_SMEM_BYTES>>>(qkv, mask, y);
    }

    // 3) out = y @ w_o^T : M=8192, N=2048, K=2048  (mma.sync tf32)
    {
        dim3 grid(CD / 128, (CB * CT) / 128);
        sgemm_tc<<<grid, 256>>>(y, w_o, out, CB * CT, CD, CD);
    }
}

// round 11
// speedup vs baseline: 4.5169x; 1.0395x over previous
#include <cuda_runtime.h>
#include <cstdint>

// Problem constants
#define CB 4
#define CT 2048
#define CD 2048
#define CH 16
#define CHD 128
#define QKVD (3 * CD)   // 6144

// Scratch (allocation-free rule: __device__ globals)
__device__ float g_qkv[(size_t)CB * CT * QKVD];   // [b, t, 6144]  (q | k | v)
__device__ float g_y[(size_t)CB * CT * CD];       // [b, t, h*128+hd]

__device__ __forceinline__ uint32_t f2tf32(float f) {
    uint32_t r;
    asm("cvt.rna.tf32.f32 %0, %1;" : "=r"(r) : "f"(f));
    return r;
}

__device__ __forceinline__ float ex2(float x) {
    float r;
    asm("ex2.approx.f32 %0, %1;" : "=f"(r) : "f"(x));
    return r;
}

__device__ __forceinline__ void mma_tf32(
    float& c0, float& c1, float& c2, float& c3,
    uint32_t a0, uint32_t a1, uint32_t a2, uint32_t a3,
    uint32_t b0, uint32_t b1)
{
    asm volatile(
        "mma.sync.aligned.m16n8k8.row.col.f32.tf32.tf32.f32 "
        "{%0,%1,%2,%3}, {%4,%5,%6,%7}, {%8,%9}, {%0,%1,%2,%3};"
        : "+f"(c0), "+f"(c1), "+f"(c2), "+f"(c3)
        : "r"(a0), "r"(a1), "r"(a2), "r"(a3), "r"(b0), "r"(b1));
}

__device__ __forceinline__ void ldsm_x4(
    uint32_t& r0, uint32_t& r1, uint32_t& r2, uint32_t& r3, uint32_t addr)
{
    asm volatile(
        "ldmatrix.sync.aligned.m8n8.x4.shared.b16 {%0,%1,%2,%3}, [%4];"
        : "=r"(r0), "=r"(r1), "=r"(r2), "=r"(r3) : "r"(addr));
}

// Per-lane byte offset for an A-fragment ldmatrix (m16 x k8 tile)
__device__ __forceinline__ uint32_t a_lane_off(int lane, int strideW) {
    return (uint32_t)((((lane & 7) + ((lane >> 3) & 1) * 8) * strideW
                       + (lane >> 4) * 4) * 4);
}
// Per-lane byte offset for a B-fragment ldmatrix covering 2 n8 tiles
__device__ __forceinline__ uint32_t b_lane_off(int lane, int strideW) {
    return (uint32_t)(((((lane >> 4) & 1) * 8 + (lane & 7)) * strideW
                       + ((lane >> 3) & 1) * 4) * 4);
}

// ===========================================================================
// Tensor-core (mma.sync tf32) NT GEMM: C[M,N] = A[M,K] @ B[N,K]^T
// CTA tile 128x256, BK=16, 256 threads = 8 warps (2 m x 4 n), warp tile 64x64.
// Double-buffered dynamic smem, single __syncthreads per stage, ldmatrix.
// ===========================================================================
#define SAST 20
#define A_BUF_W (128 * SAST)            // words per A buffer
#define B_BUF_W (256 * SAST)            // words per B buffer
#define SGEMM_SMEM_BYTES ((2 * A_BUF_W + 2 * B_BUF_W) * 4)   // 61440

__global__ __launch_bounds__(256, 1) void sgemm_tc(
    const float* __restrict__ A, const float* __restrict__ Bm,
    float* __restrict__ C, int M, int N, int K)
{
    extern __shared__ uint32_t smw[];
    uint32_t* As = smw;                      // [2][128*SAST]
    uint32_t* Bs = smw + 2 * A_BUF_W;        // [2][256*SAST]

    const int tid = threadIdx.x;
    const int wid = tid >> 5;
    const int lane = tid & 31;
    const int g = lane >> 2;      // 0..7
    const int q = lane & 3;       // 0..3

    const int warp_m = wid & 1;           // 0..1 -> m offset *64
    const int warp_n = wid >> 1;          // 0..3 -> n offset *64

    const int rowBase = blockIdx.y * 128;
    const int colBase = blockIdx.x * 256;

    // Global loaders: row = tid>>2 (+64k), col4 = tid&3
    const int lrow = tid >> 2;            // 0..63
    const int lc4 = (tid & 3) * 4;        // 0,4,8,12
    const float* Ap0 = A + (size_t)(rowBase + lrow) * K + lc4;
    const float* Ap1 = Ap0 + (size_t)64 * K;
    const float* Bp0 = Bm + (size_t)(colBase + lrow) * K + lc4;
    const float* Bp1 = Bp0 + (size_t)64 * K;
    const float* Bp2 = Bp0 + (size_t)128 * K;
    const float* Bp3 = Bp0 + (size_t)192 * K;

    const uint32_t aSm = (uint32_t)__cvta_generic_to_shared(As);
    const uint32_t bSm = (uint32_t)__cvta_generic_to_shared(Bs);
    const uint32_t aFrag0 = aSm + a_lane_off(lane, SAST)
                          + (uint32_t)(warp_m * 64 * SAST * 4);
    const uint32_t bFrag0 = bSm + b_lane_off(lane, SAST)
                          + (uint32_t)(warp_n * 64 * SAST * 4);

    float acc[4][8][4];
#pragma unroll
    for (int mt = 0; mt < 4; mt++)
#pragma unroll
        for (int nt = 0; nt < 8; nt++)
#pragma unroll
            for (int c = 0; c < 4; c++) acc[mt][nt][c] = 0.0f;

    const int nstages = K >> 4;   // K/16

    // Prologue: stage 0 into buffer 0
    {
        float4 ra0 = *(const float4*)(Ap0);
        float4 ra1 = *(const float4*)(Ap1);
        float4 rb0 = *(const float4*)(Bp0);
        float4 rb1 = *(const float4*)(Bp1);
        float4 rb2 = *(const float4*)(Bp2);
        float4 rb3 = *(const float4*)(Bp3);
        *(uint4*)&As[lrow * SAST + lc4] =
            make_uint4(f2tf32(ra0.x), f2tf32(ra0.y), f2tf32(ra0.z), f2tf32(ra0.w));
        *(uint4*)&As[(lrow + 64) * SAST + lc4] =
            make_uint4(f2tf32(ra1.x), f2tf32(ra1.y), f2tf32(ra1.z), f2tf32(ra1.w));
        *(uint4*)&Bs[lrow * SAST + lc4] =
            make_uint4(f2tf32(rb0.x), f2tf32(rb0.y), f2tf32(rb0.z), f2tf32(rb0.w));
        *(uint4*)&Bs[(lrow + 64) * SAST + lc4] =
            make_uint4(f2tf32(rb1.x), f2tf32(rb1.y), f2tf32(rb1.z), f2tf32(rb1.w));
        *(uint4*)&Bs[(lrow + 128) * SAST + lc4] =
            make_uint4(f2tf32(rb2.x), f2tf32(rb2.y), f2tf32(rb2.z), f2tf32(rb2.w));
        *(uint4*)&Bs[(lrow + 192) * SAST + lc4] =
            make_uint4(f2tf32(rb3.x), f2tf32(rb3.y), f2tf32(rb3.z), f2tf32(rb3.w));
    }
    __syncthreads();

    for (int s = 0; s < nstages; s++) {
        const int buf = s & 1;
        const uint32_t aOff = (uint32_t)(buf * A_BUF_W * 4);
        const uint32_t bOff = (uint32_t)(buf * B_BUF_W * 4);

        // Issue next-stage global loads early
        float4 ra0, ra1, rb0, rb1, rb2, rb3;
        if (s + 1 < nstages) {
            const int koff = (s + 1) << 4;
            ra0 = *(const float4*)(Ap0 + koff);
            ra1 = *(const float4*)(Ap1 + koff);
            rb0 = *(const float4*)(Bp0 + koff);
            rb1 = *(const float4*)(Bp1 + koff);
            rb2 = *(const float4*)(Bp2 + koff);
            rb3 = *(const float4*)(Bp3 + koff);
        }

        // Compute on current buffer
#pragma unroll
        for (int kk = 0; kk < 16; kk += 8) {
            uint32_t afr[4][4];
#pragma unroll
            for (int mt = 0; mt < 4; mt++)
                ldsm_x4(afr[mt][0], afr[mt][1], afr[mt][2], afr[mt][3],
                        aFrag0 + aOff
                        + (uint32_t)((mt * 16 * SAST + kk) * 4));
#pragma unroll
            for (int ntp = 0; ntp < 4; ntp++) {
                uint32_t b0, b1, b2, b3;
                ldsm_x4(b0, b1, b2, b3,
                        bFrag0 + bOff
                        + (uint32_t)((ntp * 16 * SAST + kk) * 4));
#pragma unroll
                for (int mt = 0; mt < 4; mt++) {
                    mma_tf32(acc[mt][2 * ntp][0], acc[mt][2 * ntp][1],
                             acc[mt][2 * ntp][2], acc[mt][2 * ntp][3],
                             afr[mt][0], afr[mt][1], afr[mt][2], afr[mt][3],
                             b0, b1);
                    mma_tf32(acc[mt][2 * ntp + 1][0], acc[mt][2 * ntp + 1][1],
                             acc[mt][2 * ntp + 1][2], acc[mt][2 * ntp + 1][3],
                             afr[mt][0], afr[mt][1], afr[mt][2], afr[mt][3],
                             b2, b3);
                }
            }
        }

        // Stage s+1 into the other buffer
        if (s + 1 < nstages) {
            uint32_t* An = As + (buf ^ 1) * A_BUF_W;
            uint32_t* Bn = Bs + (buf ^ 1) * B_BUF_W;
            *(uint4*)&An[lrow * SAST + lc4] =
                make_uint4(f2tf32(ra0.x), f2tf32(ra0.y), f2tf32(ra0.z), f2tf32(ra0.w));
            *(uint4*)&An[(lrow + 64) * SAST + lc4] =
                make_uint4(f2tf32(ra1.x), f2tf32(ra1.y), f2tf32(ra1.z), f2tf32(ra1.w));
            *(uint4*)&Bn[lrow * SAST + lc4] =
                make_uint4(f2tf32(rb0.x), f2tf32(rb0.y), f2tf32(rb0.z), f2tf32(rb0.w));
            *(uint4*)&Bn[(lrow + 64) * SAST + lc4] =
                make_uint4(f2tf32(rb1.x), f2tf32(rb1.y), f2tf32(rb1.z), f2tf32(rb1.w));
            *(uint4*)&Bn[(lrow + 128) * SAST + lc4] =
                make_uint4(f2tf32(rb2.x), f2tf32(rb2.y), f2tf32(rb2.z), f2tf32(rb2.w));
            *(uint4*)&Bn[(lrow + 192) * SAST + lc4] =
                make_uint4(f2tf32(rb3.x), f2tf32(rb3.y), f2tf32(rb3.z), f2tf32(rb3.w));
            __syncthreads();
        }
    }

    // Epilogue
#pragma unroll
    for (int mt = 0; mt < 4; mt++) {
        const int m0 = rowBase + warp_m * 64 + mt * 16;
#pragma unroll
        for (int nt = 0; nt < 8; nt++) {
            const int n0 = colBase + warp_n * 64 + nt * 8;
            *(float2*)(C + (size_t)(m0 + g) * N + n0 + 2 * q) =
                make_float2(acc[mt][nt][0], acc[mt][nt][1]);
            *(float2*)(C + (size_t)(m0 + g + 8) * N + n0 + 2 * q) =
                make_float2(acc[mt][nt][2], acc[mt][nt][3]);
        }
    }
}

// ===========================================================================
// Tensor-core flash attention (tf32 mma, online softmax, exp2 domain).
// Unchanged from R10.
// ===========================================================================
#define FQ 128
#define FKT 64
#define QST 132
#define PST 68
#define VTST 68

#define FLASH_SMEM_FLOATS (FQ * QST + FKT * QST + CHD * VTST + FQ * PST + FKT)
#define FLASH_SMEM_BYTES (FLASH_SMEM_FLOATS * 4)

__global__ __launch_bounds__(256, 1) void flash_attn_tc(
    const float* __restrict__ qkv, const int* __restrict__ mask,
    float* __restrict__ y)
{
    extern __shared__ uint32_t smu[];
    uint32_t* Qs = smu;                       // FQ x QST (tf32 bits)
    uint32_t* Ks = Qs + FQ * QST;             // FKT x QST
    uint32_t* Vt = Ks + FKT * QST;            // CHD x VTST (transposed V)
    uint32_t* Ps = Vt + CHD * VTST;           // FQ x PST
    float* bias = (float*)(Ps + FQ * PST);    // FKT

    const int qt = blockIdx.x;                // 0..15
    const int bh = blockIdx.y;                // 0..63
    const int b = bh / CH;
    const int h = bh % CH;

    const int tid = threadIdx.x;
    const int wid = tid >> 5;                 // 0..7
    const int lane = tid & 31;
    const int g = lane >> 2;                  // 0..7
    const int q = lane & 3;                   // 0..3
    const int m0 = wid * 16;                  // warp's query-row base

    const size_t baseQ = (size_t)b * CT * QKVD + (size_t)h * CHD;
    const size_t baseK = baseQ + CD;
    const size_t baseV = baseQ + 2 * CD;
    const int q0 = qt * FQ;

    const uint32_t qSm = (uint32_t)__cvta_generic_to_shared(Qs);
    const uint32_t kSm = (uint32_t)__cvta_generic_to_shared(Ks);
    const uint32_t vSm = (uint32_t)__cvta_generic_to_shared(Vt);
    const uint32_t pSm = (uint32_t)__cvta_generic_to_shared(Ps);

    const uint32_t aQ = qSm + a_lane_off(lane, QST) + (uint32_t)(m0 * QST * 4);
    const uint32_t bK = kSm + b_lane_off(lane, QST);
    const uint32_t aP = pSm + a_lane_off(lane, PST) + (uint32_t)(m0 * PST * 4);
    const uint32_t bV = vSm + b_lane_off(lane, VTST);

    // Load Q tile (scaled by 1/sqrt(HD) * log2(e), tf32)
    const float qscale = 0.08838834764831845f * 1.4426950408889634f;
#pragma unroll
    for (int i = 0; i < 16; i++) {
        int idx = i * 256 + tid;
        int r = idx >> 5;
        int c = (idx & 31) * 4;
        float4 v = *(const float4*)(qkv + baseQ + (size_t)(q0 + r) * QKVD + c);
        *(uint4*)&Qs[r * QST + c] = make_uint4(
            f2tf32(v.x * qscale), f2tf32(v.y * qscale),
            f2tf32(v.z * qscale), f2tf32(v.w * qscale));
    }

    float acc[16][4];
#pragma unroll
    for (int nt = 0; nt < 16; nt++)
#pragma unroll
        for (int c = 0; c < 4; c++) acc[nt][c] = 0.0f;
    float m_r0 = -1e30f, m_r1 = -1e30f;
    float l_r0 = 0.0f, l_r1 = 0.0f;

    const int vk = tid & 63;          // token within k-tile
    const int vcg_base = tid >> 6;    // 0..3

    for (int kt0 = 0; kt0 < CT; kt0 += FKT) {
        __syncthreads();

        // Load K tile (row-major, tf32)
#pragma unroll
        for (int i = 0; i < 8; i++) {
            int idx = i * 256 + tid;
            int r = idx >> 5;
            int c = (idx & 31) * 4;
            float4 kv = *(const float4*)(qkv + baseK + (size_t)(kt0 + r) * QKVD + c);
            *(uint4*)&Ks[r * QST + c] = make_uint4(
                f2tf32(kv.x), f2tf32(kv.y), f2tf32(kv.z), f2tf32(kv.w));
        }
        // Load V tile TRANSPOSED: Vt[d][k]
#pragma unroll
        for (int i = 0; i < 8; i++) {
            int cg = vcg_base + i * 4;    // 0..31
            float4 vv = *(const float4*)(qkv + baseV
                                         + (size_t)(kt0 + vk) * QKVD + cg * 4);
            Vt[(cg * 4 + 0) * VTST + vk] = f2tf32(vv.x);
            Vt[(cg * 4 + 1) * VTST + vk] = f2tf32(vv.y);
            Vt[(cg * 4 + 2) * VTST + vk] = f2tf32(vv.z);
            Vt[(cg * 4 + 3) * VTST + vk] = f2tf32(vv.w);
        }
        if (tid < FKT)
            bias[tid] = mask[b * CT + kt0 + tid] ? 0.0f : -1e30f;
        __syncthreads();

        // ---- S = Q @ K^T (16 x 64 per warp) ----
        float s[8][4];
#pragma unroll
        for (int nt = 0; nt < 8; nt++)
#pragma unroll
            for (int c = 0; c < 4; c++) s[nt][c] = 0.0f;

#pragma unroll
        for (int ks = 0; ks < 16; ks++) {
            const uint32_t kkB = (uint32_t)(ks * 8 * 4);
            uint32_t a0, a1, a2, a3;
            ldsm_x4(a0, a1, a2, a3, aQ + kkB);
#pragma unroll
            for (int ntp = 0; ntp < 4; ntp++) {
                uint32_t b0, b1, b2, b3;
                ldsm_x4(b0, b1, b2, b3,
                        bK + (uint32_t)(ntp * 16 * QST * 4) + kkB);
                mma_tf32(s[2 * ntp][0], s[2 * ntp][1],
                         s[2 * ntp][2], s[2 * ntp][3],
                         a0, a1, a2, a3, b0, b1);
                mma_tf32(s[2 * ntp + 1][0], s[2 * ntp + 1][1],
                         s[2 * ntp + 1][2], s[2 * ntp + 1][3],
                         a0, a1, a2, a3, b2, b3);
            }
        }

        // mask bias
#pragma unroll
        for (int nt = 0; nt < 8; nt++) {
            float2 bb = *(const float2*)&bias[nt * 8 + 2 * q];
            s[nt][0] += bb.x; s[nt][1] += bb.y;
            s[nt][2] += bb.x; s[nt][3] += bb.y;
        }

        // row maxes
        float tm0 = -1e30f, tm1 = -1e30f;
#pragma unroll
        for (int nt = 0; nt < 8; nt++) {
            tm0 = fmaxf(tm0, fmaxf(s[nt][0], s[nt][1]));
            tm1 = fmaxf(tm1, fmaxf(s[nt][2], s[nt][3]));
        }
        tm0 = fmaxf(tm0, __shfl_xor_sync(0xffffffffu, tm0, 1));
        tm0 = fmaxf(tm0, __shfl_xor_sync(0xffffffffu, tm0, 2));
        tm1 = fmaxf(tm1, __shfl_xor_sync(0xffffffffu, tm1, 1));
        tm1 = fmaxf(tm1, __shfl_xor_sync(0xffffffffu, tm1, 2));

        const float mn0 = fmaxf(m_r0, tm0);
        const float mn1 = fmaxf(m_r1, tm1);
        const float corr0 = ex2(m_r0 - mn0);
        const float corr1 = ex2(m_r1 - mn1);
        m_r0 = mn0; m_r1 = mn1;

        float ps0 = 0.0f, ps1 = 0.0f;
#pragma unroll
        for (int nt = 0; nt < 8; nt++) {
            float p0 = ex2(s[nt][0] - mn0);
            float p1 = ex2(s[nt][1] - mn0);
            float p2 = ex2(s[nt][2] - mn1);
            float p3 = ex2(s[nt][3] - mn1);
            ps0 += p0 + p1;
            ps1 += p2 + p3;
            *(uint2*)&Ps[(m0 + g) * PST + nt * 8 + 2 * q] =
                make_uint2(f2tf32(p0), f2tf32(p1));
            *(uint2*)&Ps[(m0 + g + 8) * PST + nt * 8 + 2 * q] =
                make_uint2(f2tf32(p2), f2tf32(p3));
        }
        ps0 += __shfl_xor_sync(0xffffffffu, ps0, 1);
        ps0 += __shfl_xor_sync(0xffffffffu, ps0, 2);
        ps1 += __shfl_xor_sync(0xffffffffu, ps1, 1);
        ps1 += __shfl_xor_sync(0xffffffffu, ps1, 2);
        l_r0 = l_r0 * corr0 + ps0;
        l_r1 = l_r1 * corr1 + ps1;

#pragma unroll
        for (int nt = 0; nt < 16; nt++) {
            acc[nt][0] *= corr0; acc[nt][1] *= corr0;
            acc[nt][2] *= corr1; acc[nt][3] *= corr1;
        }
        __syncwarp();

        // ---- O += P @ V (16 x 128 per warp) ----
#pragma unroll
        for (int ks = 0; ks < 8; ks++) {
            const uint32_t kkB = (uint32_t)(ks * 8 * 4);
            uint32_t a0, a1, a2, a3;
            ldsm_x4(a0, a1, a2, a3, aP + kkB);
#pragma unroll
            for (int ntp = 0; ntp < 8; ntp++) {
                uint32_t b0, b1, b2, b3;
                ldsm_x4(b0, b1, b2, b3,
                        bV + (uint32_t)(ntp * 16 * VTST * 4) + kkB);
                mma_tf32(acc[2 * ntp][0], acc[2 * ntp][1],
                         acc[2 * ntp][2], acc[2 * ntp][3],
                         a0, a1, a2, a3, b0, b1);
                mma_tf32(acc[2 * ntp + 1][0], acc[2 * ntp + 1][1],
                         acc[2 * ntp + 1][2], acc[2 * ntp + 1][3],
                         a0, a1, a2, a3, b2, b3);
            }
        }
    }

    // Normalize and write y
    const float inv0 = 1.0f / l_r0;
    const float inv1 = 1.0f / l_r1;
    const int row0 = q0 + m0 + g;
    const int row1 = row0 + 8;
    float* y0 = y + (size_t)(b * CT + row0) * CD + h * CHD;
    float* y1 = y + (size_t)(b * CT + row1) * CD + h * CHD;
#pragma unroll
    for (int nt = 0; nt < 16; nt++) {
        const int col = nt * 8 + 2 * q;
        *(float2*)(y0 + col) = make_float2(acc[nt][0] * inv0, acc[nt][1] * inv0);
        *(float2*)(y1 + col) = make_float2(acc[nt][2] * inv1, acc[nt][3] * inv1);
    }
}

// ---------------------------------------------------------------------------
extern "C" void kernel_launch(void* const* d_in, const int* in_sizes, int n_in,
                              void* d_out, int out_size)
{
    const float* x      = (const float*)d_in[0];
    const int*   mask   = (const int*)d_in[1];
    const float* w_qkv  = (const float*)d_in[2];
    const float* w_o    = (const float*)d_in[3];
    float*       out    = (float*)d_out;

    float* qkv = nullptr;
    float* y   = nullptr;
    cudaGetSymbolAddress((void**)&qkv, g_qkv);
    cudaGetSymbolAddress((void**)&y, g_y);

    cudaFuncSetAttribute(sgemm_tc,
                         cudaFuncAttributeMaxDynamicSharedMemorySize,
                         SGEMM_SMEM_BYTES);
    cudaFuncSetAttribute(flash_attn_tc,
                         cudaFuncAttributeMaxDynamicSharedMemorySize,
                         FLASH_SMEM_BYTES);

    // 1) qkv = x @ w_qkv^T : M=8192, N=6144, K=2048  (mma.sync tf32)
    {
        dim3 grid(QKVD / 256, (CB * CT) / 128);
        sgemm_tc<<<grid, 256, SGEMM_SMEM_BYTES>>>(x, w_qkv, qkv, CB * CT, QKVD, CD);
    }

    // 2) fused attention -> y (mma.sync tf32 + ldmatrix)
    {
        dim3 grid(CT / FQ, CB * CH);
        flash_attn_tc<<<grid, 256, FLASH_SMEM_BYTES>>>(qkv, mask, y);
    }

    // 3) out = y @ w_o^T : M=8192, N=2048, K=2048  (mma.sync tf32)
    {
        dim3 grid(CD / 256, (CB * CT) / 128);
        sgemm_tc<<<grid, 256, SGEMM_SMEM_BYTES>>>(y, w_o, out, CB * CT, CD, CD);
    }
}